// round 4
// baseline (speedup 1.0000x reference)
#include <cuda_runtime.h>
#include <cstdint>

// Problem constants
#define NN 50000
#define DD 128
#define EE 625000

typedef unsigned long long u64;

// Scratch (allocation-free rule: __device__ globals)
__device__ float g_agg[(size_t)NN * DD];
__device__ float g_h[(size_t)NN * DD];
__device__ int g_deg[NN];
__device__ int g_row[NN + 1];
__device__ int g_cur[NN];
__device__ int g_csrc[EE];

// ---------------------------------------------------------------------------
// CSR build step 1: zero degree counters
// ---------------------------------------------------------------------------
__global__ void zero_deg_kernel(int* __restrict__ deg) {
    int i = blockIdx.x * blockDim.x + threadIdx.x;
    if (i < NN) deg[i] = 0;
}

// CSR build step 2: histogram of dst
__global__ void hist_kernel(const int* __restrict__ ei, int* __restrict__ deg) {
    int e = blockIdx.x * blockDim.x + threadIdx.x;
    if (e < EE) atomicAdd(&deg[ei[EE + e]], 1);
}

// CSR build step 3: exclusive scan of degrees -> row offsets (+ cursor copy).
// Single block, 1024 threads, each owns a contiguous chunk.
__global__ __launch_bounds__(1024, 1)
void scan_kernel(const int* __restrict__ deg,
                 int* __restrict__ row, int* __restrict__ cur) {
    __shared__ int partial[1024];
    int tid = threadIdx.x;
    const int chunk = (NN + 1023) / 1024;  // 49
    int start = tid * chunk;
    int mysum = 0;
    for (int i = 0; i < chunk; i++) {
        int idx = start + i;
        if (idx < NN) mysum += deg[idx];
    }
    partial[tid] = mysum;
    __syncthreads();
    // Hillis-Steele inclusive scan
    for (int off = 1; off < 1024; off <<= 1) {
        int v = (tid >= off) ? partial[tid - off] : 0;
        __syncthreads();
        partial[tid] += v;
        __syncthreads();
    }
    int run = partial[tid] - mysum;  // exclusive prefix of my chunk
    for (int i = 0; i < chunk; i++) {
        int idx = start + i;
        if (idx < NN) {
            row[idx] = run;
            cur[idx] = run;
            run += deg[idx];
        }
    }
    if (tid == 0) row[NN] = EE;
}

// CSR build step 4: fill permuted src list
__global__ void fill_kernel(const int* __restrict__ ei,
                            int* __restrict__ cur, int* __restrict__ csrc) {
    int e = blockIdx.x * blockDim.x + threadIdx.x;
    if (e < EE) {
        int s = ei[e];
        int d = ei[EE + e];
        int pos = atomicAdd(&cur[d], 1);
        csrc[pos] = s;
    }
}

// ---------------------------------------------------------------------------
// Gather-aggregate: one warp per dst node. Atomic-free.
//   agg[d] = sum over neighbors s of feat[s]   (128 floats = 32 x float4)
// Indices read 32-wide per warp batch, broadcast via shfl; feature loads
// 4-way batched for MLP.
// ---------------------------------------------------------------------------
__global__ __launch_bounds__(256, 1)
void gather_kernel(const float* __restrict__ feat,
                   const int* __restrict__ row,
                   const int* __restrict__ csrc,
                   float* __restrict__ agg) {
    int d = (blockIdx.x * blockDim.x + threadIdx.x) >> 5;
    int lane = threadIdx.x & 31;
    if (d >= NN) return;
    int beg = __ldg(&row[d]);
    int end = __ldg(&row[d + 1]);

    float4 acc = make_float4(0.f, 0.f, 0.f, 0.f);
    for (int b = beg; b < end; b += 32) {
        int n = min(32, end - b);
        int myidx = (lane < n) ? __ldg(&csrc[b + lane]) : 0;
        int t = 0;
        for (; t + 4 <= n; t += 4) {
            int s0 = __shfl_sync(0xffffffffu, myidx, t);
            int s1 = __shfl_sync(0xffffffffu, myidx, t + 1);
            int s2 = __shfl_sync(0xffffffffu, myidx, t + 2);
            int s3 = __shfl_sync(0xffffffffu, myidx, t + 3);
            float4 v0 = ((const float4*)(feat + (size_t)s0 * DD))[lane];
            float4 v1 = ((const float4*)(feat + (size_t)s1 * DD))[lane];
            float4 v2 = ((const float4*)(feat + (size_t)s2 * DD))[lane];
            float4 v3 = ((const float4*)(feat + (size_t)s3 * DD))[lane];
            acc.x += v0.x; acc.y += v0.y; acc.z += v0.z; acc.w += v0.w;
            acc.x += v1.x; acc.y += v1.y; acc.z += v1.z; acc.w += v1.w;
            acc.x += v2.x; acc.y += v2.y; acc.z += v2.z; acc.w += v2.w;
            acc.x += v3.x; acc.y += v3.y; acc.z += v3.z; acc.w += v3.w;
        }
        for (; t < n; t++) {
            int s = __shfl_sync(0xffffffffu, myidx, t);
            float4 v = ((const float4*)(feat + (size_t)s * DD))[lane];
            acc.x += v.x; acc.y += v.y; acc.z += v.z; acc.w += v.w;
        }
    }
    ((float4*)(agg + (size_t)d * DD))[lane] = acc;
}

// ---------------------------------------------------------------------------
// Fused dual GEMM with packed f32x2 FMA (FFMA2) — unchanged from R3.
// ---------------------------------------------------------------------------
#define KT 64
#define AST 68
#define GEMM_SMEM ((2 * 128 * 128 + 2 * 128 * AST) * sizeof(float))

__device__ __forceinline__ u64 pack2(float a) {
    u64 r;
    asm("mov.b64 %0, {%1, %1};" : "=l"(r) : "f"(a));
    return r;
}
__device__ __forceinline__ u64 ffma2(u64 a, u64 b, u64 c) {
    u64 d;
    asm("fma.rn.f32x2 %0, %1, %2, %3;" : "=l"(d) : "l"(a), "l"(b), "l"(c));
    return d;
}

__global__ __launch_bounds__(256, 1)
void gemm_kernel(const float* __restrict__ A,
                 const float* __restrict__ X,
                 const float* __restrict__ Wrel,
                 const float* __restrict__ Wroot,
                 const float* __restrict__ bias,
                 float* __restrict__ out,
                 int relu) {
    extern __shared__ float sm[];
    float* Wr = sm;                   // 128*128
    float* Wo = Wr + 128 * 128;       // 128*128
    float* As = Wo + 128 * 128;       // 128*AST
    float* Xs = As + 128 * AST;       // 128*AST

    int tid = threadIdx.x;
    int row0 = blockIdx.x * 128;
    int tx = tid & 15;
    int ty = tid >> 4;

    for (int i = tid; i < 128 * 128 / 4; i += 256) {
        ((float4*)Wr)[i] = ((const float4*)Wrel)[i];
        ((float4*)Wo)[i] = ((const float4*)Wroot)[i];
    }

    u64 acc[8][4];
#pragma unroll
    for (int i = 0; i < 8; i++)
#pragma unroll
        for (int j = 0; j < 4; j++) acc[i][j] = 0ull;

    for (int stage = 0; stage < 2; stage++) {
        int kb = stage * KT;
        __syncthreads();
        for (int i = tid; i < 128 * 16; i += 256) {
            int r = i >> 4, c = i & 15;
            int grow = row0 + r;
            float4 av, xv;
            if (grow < NN) {
                av = ((const float4*)(A + (size_t)grow * DD + kb))[c];
                xv = ((const float4*)(X + (size_t)grow * DD + kb))[c];
            } else {
                av = make_float4(0.f, 0.f, 0.f, 0.f);
                xv = av;
            }
            ((float4*)(As + r * AST))[c] = av;
            ((float4*)(Xs + r * AST))[c] = xv;
        }
        __syncthreads();

#pragma unroll 2
        for (int kk = 0; kk < KT; kk++) {
            const float* wrk = Wr + (kb + kk) * 128;
            const float* wok = Wo + (kb + kk) * 128;
            u64 wr2[4], wo2[4];
#pragma unroll
            for (int j = 0; j < 4; j++) {
                wr2[j] = *(const u64*)(wrk + tx * 2 + j * 32);
                wo2[j] = *(const u64*)(wok + tx * 2 + j * 32);
            }
            u64 a2[8], x2[8];
#pragma unroll
            for (int i = 0; i < 8; i++) {
                a2[i] = pack2(As[(ty * 8 + i) * AST + kk]);
                x2[i] = pack2(Xs[(ty * 8 + i) * AST + kk]);
            }
#pragma unroll
            for (int i = 0; i < 8; i++)
#pragma unroll
                for (int j = 0; j < 4; j++) {
                    acc[i][j] = ffma2(a2[i], wr2[j], acc[i][j]);
                    acc[i][j] = ffma2(x2[i], wo2[j], acc[i][j]);
                }
        }
    }

    float b0[4], b1[4];
#pragma unroll
    for (int j = 0; j < 4; j++) {
        int c = tx * 2 + j * 32;
        b0[j] = __ldg(&bias[c]);
        b1[j] = __ldg(&bias[c + 1]);
    }
#pragma unroll
    for (int i = 0; i < 8; i++) {
        int grow = row0 + ty * 8 + i;
        if (grow < NN) {
#pragma unroll
            for (int j = 0; j < 4; j++) {
                int c = tx * 2 + j * 32;
                float lo, hi;
                asm("mov.b64 {%0, %1}, %2;" : "=f"(lo), "=f"(hi) : "l"(acc[i][j]));
                lo += b0[j];
                hi += b1[j];
                if (relu) { lo = fmaxf(lo, 0.f); hi = fmaxf(hi, 0.f); }
                *(float2*)(out + (size_t)grow * DD + c) = make_float2(lo, hi);
            }
        }
    }
}

// ---------------------------------------------------------------------------
// Launch
// ---------------------------------------------------------------------------
extern "C" void kernel_launch(void* const* d_in, const int* in_sizes, int n_in,
                              void* d_out, int out_size) {
    const float* x       = (const float*)d_in[0];
    const int*   ei      = (const int*)d_in[1];   // int32 (JAX x64 disabled)
    const float* W1_rel  = (const float*)d_in[2];
    const float* b1_rel  = (const float*)d_in[3];
    const float* W1_root = (const float*)d_in[4];
    const float* W2_rel  = (const float*)d_in[5];
    const float* b2_rel  = (const float*)d_in[6];
    const float* W2_root = (const float*)d_in[7];
    float*       out     = (float*)d_out;

    float *agg, *h;
    int *deg, *row, *cur, *csrc;
    cudaGetSymbolAddress((void**)&agg, g_agg);
    cudaGetSymbolAddress((void**)&h, g_h);
    cudaGetSymbolAddress((void**)&deg, g_deg);
    cudaGetSymbolAddress((void**)&row, g_row);
    cudaGetSymbolAddress((void**)&cur, g_cur);
    cudaGetSymbolAddress((void**)&csrc, g_csrc);

    cudaFuncSetAttribute(gemm_kernel,
                         cudaFuncAttributeMaxDynamicSharedMemorySize,
                         (int)GEMM_SMEM);

    const int egrid = (EE + 255) / 256;
    const int ngrid = (NN + 255) / 256;
    const int wgrid = (NN * 32 + 255) / 256;   // warp per node
    const int ggrid = (NN + 127) / 128;

    // Build CSR (once per launch; shared by both layers)
    zero_deg_kernel<<<ngrid, 256>>>(deg);
    hist_kernel<<<egrid, 256>>>(ei, deg);
    scan_kernel<<<1, 1024>>>(deg, row, cur);
    fill_kernel<<<egrid, 256>>>(ei, cur, csrc);

    // Layer 1
    gather_kernel<<<wgrid, 256>>>(x, row, csrc, agg);
    gemm_kernel<<<ggrid, 256, GEMM_SMEM>>>(agg, x, W1_rel, W1_root, b1_rel, h, 1);

    // Layer 2
    gather_kernel<<<wgrid, 256>>>(h, row, csrc, agg);
    gemm_kernel<<<ggrid, 256, GEMM_SMEM>>>(agg, h, W2_rel, W2_root, b2_rel, out, 0);
}